// round 13
// baseline (speedup 1.0000x reference)
#include <cuda_runtime.h>

#define B_DIM   256
#define OUT_DIM 256
#define IN_DIM  256
#define G_DIM   8
#define LOG2E   1.44269504088896340736f
#define LN2     0.69314718055994530942f

#define OT    8          // o per CTA (4 o-pairs)
#define BT    64         // b per CTA (32 b-pairs)
#define IC    32         // i-chunk = whole per-CTA i range (single barrier phase)
#define Z     8
#define IPART (IN_DIM / Z)      // 32 == IC

// shared layout strides (bank-audited)
#define AB_F4_PER_II 41         // 4 opairs * 10 float4 + 1 pad  (656B per ii)
#define XN_STR 68               // floats per ii row (272B = 17*16B)
#define KP_STR 36               // u16 per bpair row (72B = 9*8B)

// Precomputed scratch (device globals; no allocation).
__device__ float          g_xn[IN_DIM * B_DIM];            // [i][b]: tanh(x)*log2e
__device__ unsigned short g_kp[(B_DIM / 2) * IN_DIM];      // [bpair][i]: (k0*16)|(k1*16)<<8
__device__ float4         g_ABP[10][(OUT_DIM / 2) * IN_DIM];
// g_ABP[k][op*IN+i]: k<9 -> {A_k(2op), B_k(2op), A_k(2op+1), B_k(2op+1)}
//                    k=9 -> {s(2op), b'(2op), s(2op+1), b'(2op+1)}   (b' = base*ln2)

__device__ __forceinline__ float rcp_f(float a) {
    float r; asm("rcp.approx.f32 %0, %1;" : "=f"(r) : "f"(a)); return r;
}
__device__ __forceinline__ float ex2_f(float a) {
    float r; asm("ex2.approx.f32 %0, %1;" : "=f"(r) : "f"(a)); return r;
}
__device__ __forceinline__ float tanh_fast(float x) {
    float e = __expf(2.0f * x);                 // saturates correctly at +/-inf
    return 1.0f - __fdividef(2.0f, e + 1.0f);
}

// ---------------------------------------------------------------------------
// Prep: blocks [0,128) -> xn/k + zero out; blocks [128,384) -> A/B tables
// (one o per thread, float2 half-writes into the o-paired float4 cells).
// ---------------------------------------------------------------------------
__global__ __launch_bounds__(256)
void k_prep(const float* __restrict__ x,
            const float* __restrict__ w,
            const float* __restrict__ scaler,
            const float* __restrict__ base_,
            const float* __restrict__ grid,
            float* __restrict__ out)
{
    const float g0    = __ldg(grid);
    const float g7    = __ldg(grid + (G_DIM - 1));
    const float step  = (g7 - g0) * (1.0f / (float)(G_DIM - 1));
    const float inv_h = (float)(G_DIM - 1) / (g7 - g0);

    if (blockIdx.x < 128) {
        // ---- xn / k (+ zero the output buffer) ----
        int u    = blockIdx.x * 256 + threadIdx.x;   // 0..32767
        ((float2*)out)[u] = make_float2(0.f, 0.f);
        int pair = u >> 8;                           // 0..127
        int i    = u & 255;
        int b    = pair * 2;
        float xn0 = tanh_fast(x[b * IN_DIM + i]);
        float xn1 = tanh_fast(x[(b + 1) * IN_DIM + i]);
        int k0 = 1 + __float2int_rd((xn0 - g0) * inv_h);
        int k1 = 1 + __float2int_rd((xn1 - g0) * inv_h);
        k0 = max(0, min(8, k0));
        k1 = max(0, min(8, k1));
        *(float2*)&g_xn[i * B_DIM + b] = make_float2(xn0 * LOG2E, xn1 * LOG2E);
        g_kp[pair * IN_DIM + i] = (unsigned short)((k0 * 16) | ((k1 * 16) << 8));
    } else {
        // ---- A/B prefix tables: one (o,i) per thread ----
        int v = (blockIdx.x - 128) * 256 + threadIdx.x;  // o*IN + i, 0..65535
        int o = v >> 8;
        int i = v & 255;
        int idx2 = 2 * ((o >> 1) * IN_DIM + i) + (o & 1);  // float2 slot in float4 cell

        float s = scaler[v];
        float4 w0 = *(const float4*)(w + v * G_DIM);
        float4 w1 = *(const float4*)(w + v * G_DIM + 4);
        float wv[G_DIM] = {w0.x, w0.y, w0.z, w0.w, w1.x, w1.y, w1.z, w1.w};
        float Ep = __expf(s * step);
        float ep = __expf(s * g0);
        float Eq = rcp_f(Ep);
        float eq = rcp_f(ep);
        float p[G_DIM], q[G_DIM];
#pragma unroll
        for (int g = 0; g < G_DIM; g++) {
            p[g] = wv[g] * ep;  ep *= Ep;   // w_g * e^{ s*grid_g}
            q[g] = wv[g] * eq;  eq *= Eq;   // w_g * e^{-s*grid_g}
        }
        float A[9], Bv[9];
        A[0] = 0.f;
#pragma unroll
        for (int k = 0; k < 8; k++) A[k + 1] = A[k] + p[k];
        Bv[8] = 0.f;
#pragma unroll
        for (int k = 7; k >= 0; k--) Bv[k] = Bv[k + 1] + q[k];
#pragma unroll
        for (int k = 0; k < 9; k++)
            ((float2*)(g_ABP[k]))[idx2] = make_float2(A[k], Bv[k]);
        ((float2*)(g_ABP[9]))[idx2] = make_float2(s, base_[v] * LN2);
    }
}

// ---------------------------------------------------------------------------
// Main: CTA = 64b x 8o x 32i; thread = (2b x 2o); single stage + consume phase.
//   contribution = A_k*2^{-t} + B_k*2^{t} + b'*xn',  t = s*xn'
// 1024 CTAs @ 7/SM = exactly one wave.
// ---------------------------------------------------------------------------
__global__ __launch_bounds__(128, 7)
void k_main(float* __restrict__ out)
{
    __shared__ __align__(16) float4         sh_ab[IC * AB_F4_PER_II];  // 21.0KB
    __shared__ __align__(16) float          sh_xn[IC][XN_STR];         // 8.5KB
    __shared__ __align__(8)  unsigned short sh_kp[IC][KP_STR];         // 2.25KB (rows=bpair)

    const int tid   = threadIdx.x;
    const int opair = tid & 3;           // o = o0 + 2*opair (+0/1)
    const int bpair = tid >> 2;          // 0..31 -> b = b0 + 2*bpair (+0/1)
    const int o0    = blockIdx.x * OT;
    const int opg0  = blockIdx.x * (OT / 2);
    const int b0    = blockIdx.y * BT;
    const int i0    = blockIdx.z * IPART;

    // ---- stage xn: 32 ii x 64 b floats (8KB), 4 float4 per thread ----
#pragma unroll
    for (int j = 0; j < 4; j++) {
        int e  = tid + j * 128;          // 0..511
        int ii = e >> 4;
        int b4 = (e & 15) * 4;
        *(float4*)&sh_xn[ii][b4] = *(const float4*)&g_xn[(i0 + ii) * B_DIM + b0 + b4];
    }
    // ---- stage k-pack: 32 bpairs x 32 ii u16 (2KB), 2 uint2 per thread ----
#pragma unroll
    for (int j = 0; j < 2; j++) {
        int e  = tid + j * 128;          // 0..255
        int pr = e >> 3;
        int i4 = (e & 7) * 4;
        *(uint2*)&sh_kp[pr][i4] = *(const uint2*)&g_kp[(b0 / 2 + pr) * IN_DIM + i0 + i4];
    }
    // ---- stage AB cells: 10 k x 4 op x 32 ii float4 (20.5KB), 10 per thread ----
#pragma unroll
    for (int un = 0; un < 10; un++) {
        int e  = tid + un * 128;         // 0..1279
        int ii = e & 31;
        int op = (e >> 5) & 3;
        int k  = e >> 7;
        sh_ab[ii * AB_F4_PER_II + op * 10 + k] =
            g_ABP[k][(opg0 + op) * IN_DIM + i0 + ii];
    }
    __syncthreads();

    // ---- consume: 4 triples (2b x 2o) per ii per thread ----
    float acc00 = 0.f, acc01 = 0.f, acc10 = 0.f, acc11 = 0.f;
    const char* rbase = (const char*)sh_ab + opair * 160;
    const unsigned short* kpr = sh_kp[bpair];
    const float* xnr = &sh_xn[0][2 * bpair];
#pragma unroll
    for (int ii = 0; ii < IC; ii++) {
        float2 xn2 = *(const float2*)(xnr + ii * XN_STR);
        unsigned int kk = kpr[ii];
        const char* rp = rbase + ii * (AB_F4_PER_II * 16);
        float4 sbq = *(const float4*)(rp + 144);           // {s,b',s',b''}
        float4 gA  = *(const float4*)(rp + (kk & 0xFFu));  // {A,B,A',B'} @ k0 (b)
        float4 gB  = *(const float4*)(rp + (kk >> 8));     // {A,B,A',B'} @ k1 (b+1)
        float t00 = sbq.x * xn2.x;      // (o , b)
        float t01 = sbq.z * xn2.x;      // (o', b)
        float t10 = sbq.x * xn2.y;      // (o , b+1)
        float t11 = sbq.z * xn2.y;      // (o', b+1)
        float u00 = ex2_f(t00), r00 = rcp_f(u00);
        float u01 = ex2_f(t01), r01 = rcp_f(u01);
        float u10 = ex2_f(t10), r10 = rcp_f(u10);
        float u11 = ex2_f(t11), r11 = rcp_f(u11);
        acc00 = fmaf(gA.x, r00, fmaf(gA.y, u00, fmaf(sbq.y, xn2.x, acc00)));
        acc01 = fmaf(gA.z, r01, fmaf(gA.w, u01, fmaf(sbq.w, xn2.x, acc01)));
        acc10 = fmaf(gB.x, r10, fmaf(gB.y, u10, fmaf(sbq.y, xn2.y, acc10)));
        acc11 = fmaf(gB.z, r11, fmaf(gB.w, u11, fmaf(sbq.w, xn2.y, acc11)));
    }

    // Z=8: one-shot commutative atomic adds from a zeroed buffer
    int b = b0 + 2 * bpair;
    int o = o0 + 2 * opair;
    atomicAdd(&out[b * OUT_DIM + o],           acc00);
    atomicAdd(&out[b * OUT_DIM + o + 1],       acc01);
    atomicAdd(&out[(b + 1) * OUT_DIM + o],     acc10);
    atomicAdd(&out[(b + 1) * OUT_DIM + o + 1], acc11);
}

// ---------------------------------------------------------------------------
extern "C" void kernel_launch(void* const* d_in, const int* in_sizes, int n_in,
                              void* d_out, int out_size)
{
    const float* x      = (const float*)d_in[0];
    const float* w      = (const float*)d_in[1];
    const float* scaler = (const float*)d_in[2];
    const float* base   = (const float*)d_in[3];
    const float* grid   = (const float*)d_in[4];
    float* out = (float*)d_out;

    k_prep<<<384, 256>>>(x, w, scaler, base, grid, out);
    dim3 g(OUT_DIM / OT, B_DIM / BT, Z);    // 32 x 4 x 8 = 1024 CTAs
    k_main<<<g, 128>>>(out);
}

// round 14
// speedup vs baseline: 1.0015x; 1.0015x over previous
#include <cuda_runtime.h>

#define B_DIM   256
#define OUT_DIM 256
#define IN_DIM  256
#define G_DIM   8
#define LOG2E   1.44269504088896340736f
#define LN2     0.69314718055994530942f

#define OT    8          // o per CTA (4 o-pairs)
#define BT    64         // b per CTA (32 b-pairs)
#define IC    16         // i-chunk
#define Z     8
#define IPART (IN_DIM / Z)      // 32
#define NCH   (IPART / IC)      // 2

// shared layout constants
#define AB_F4_PER_II 41         // 4 opairs * 10 float4 + 1 pad  (656B per ii)
#define XN_STR 68               // floats per ii row (272B, 16B-mult)
#define KP_STR 20               // u16 per bpair row (40B, 8B-mult)

// Precomputed scratch (device globals; no allocation).
__device__ float          g_xn[IN_DIM * B_DIM];            // [i][b]: tanh(x)*log2e
__device__ unsigned short g_kp[(B_DIM / 2) * IN_DIM];      // [bpair][i]: (k0*16)|(k1*16)<<8
__device__ float4         g_ABP[10][(OUT_DIM / 2) * IN_DIM];
// g_ABP[k][op*IN+i]: k<9 -> {A_k(2op), B_k(2op), A_k(2op+1), B_k(2op+1)}
//                    k=9 -> {s(2op), b'(2op), s(2op+1), b'(2op+1)}   (b' = base*ln2)

__device__ __forceinline__ float rcp_f(float a) {
    float r; asm("rcp.approx.f32 %0, %1;" : "=f"(r) : "f"(a)); return r;
}
__device__ __forceinline__ float ex2_f(float a) {
    float r; asm("ex2.approx.f32 %0, %1;" : "=f"(r) : "f"(a)); return r;
}
__device__ __forceinline__ float tanh_fast(float x) {
    float e = __expf(2.0f * x);                 // saturates correctly at +/-inf
    return 1.0f - __fdividef(2.0f, e + 1.0f);
}

// ---------------------------------------------------------------------------
// Prep: blocks [0,128) -> xn/k + zero out; blocks [128,384) -> A/B tables
// (one o per thread, float2 half-writes into the o-paired float4 cells).
// ---------------------------------------------------------------------------
__global__ __launch_bounds__(256)
void k_prep(const float* __restrict__ x,
            const float* __restrict__ w,
            const float* __restrict__ scaler,
            const float* __restrict__ base_,
            const float* __restrict__ grid,
            float* __restrict__ out)
{
    const float g0    = __ldg(grid);
    const float g7    = __ldg(grid + (G_DIM - 1));
    const float step  = (g7 - g0) * (1.0f / (float)(G_DIM - 1));
    const float inv_h = (float)(G_DIM - 1) / (g7 - g0);

    if (blockIdx.x < 128) {
        // ---- xn / k (+ zero the output buffer) ----
        int u    = blockIdx.x * 256 + threadIdx.x;   // 0..32767
        ((float2*)out)[u] = make_float2(0.f, 0.f);
        int pair = u >> 8;                           // 0..127
        int i    = u & 255;
        int b    = pair * 2;
        float xn0 = tanh_fast(x[b * IN_DIM + i]);
        float xn1 = tanh_fast(x[(b + 1) * IN_DIM + i]);
        int k0 = 1 + __float2int_rd((xn0 - g0) * inv_h);
        int k1 = 1 + __float2int_rd((xn1 - g0) * inv_h);
        k0 = max(0, min(8, k0));
        k1 = max(0, min(8, k1));
        *(float2*)&g_xn[i * B_DIM + b] = make_float2(xn0 * LOG2E, xn1 * LOG2E);
        g_kp[pair * IN_DIM + i] = (unsigned short)((k0 * 16) | ((k1 * 16) << 8));
    } else {
        // ---- A/B prefix tables: one (o,i) per thread ----
        int v = (blockIdx.x - 128) * 256 + threadIdx.x;  // o*IN + i, 0..65535
        int o = v >> 8;
        int i = v & 255;
        int idx2 = 2 * ((o >> 1) * IN_DIM + i) + (o & 1);  // float2 slot in float4 cell

        float s = scaler[v];
        float4 w0 = *(const float4*)(w + v * G_DIM);
        float4 w1 = *(const float4*)(w + v * G_DIM + 4);
        float wv[G_DIM] = {w0.x, w0.y, w0.z, w0.w, w1.x, w1.y, w1.z, w1.w};
        float Ep = __expf(s * step);
        float ep = __expf(s * g0);
        float Eq = rcp_f(Ep);
        float eq = rcp_f(ep);
        float p[G_DIM], q[G_DIM];
#pragma unroll
        for (int g = 0; g < G_DIM; g++) {
            p[g] = wv[g] * ep;  ep *= Ep;   // w_g * e^{ s*grid_g}
            q[g] = wv[g] * eq;  eq *= Eq;   // w_g * e^{-s*grid_g}
        }
        float A[9], Bv[9];
        A[0] = 0.f;
#pragma unroll
        for (int k = 0; k < 8; k++) A[k + 1] = A[k] + p[k];
        Bv[8] = 0.f;
#pragma unroll
        for (int k = 7; k >= 0; k--) Bv[k] = Bv[k + 1] + q[k];
#pragma unroll
        for (int k = 0; k < 9; k++)
            ((float2*)(g_ABP[k]))[idx2] = make_float2(A[k], Bv[k]);
        ((float2*)(g_ABP[9]))[idx2] = make_float2(s, base_[v] * LN2);
    }
}

// ---------------------------------------------------------------------------
// Main: CTA = 64b x 8o x IPART i; thread = (2b x 2o); stage + consume.
//   contribution = A_k*2^{-t} + B_k*2^{t} + b'*xn',  t = s*xn'
// Reg-capped to 64 -> 8 CTAs/SM capacity -> 1024 CTAs in a single wave.
// ---------------------------------------------------------------------------
__global__ __launch_bounds__(128, 8)
void k_main(float* __restrict__ out)
{
    __shared__ __align__(16) float          sh_ab[IC * AB_F4_PER_II * 4];  // 10.5KB
    __shared__ __align__(16) float          sh_xn[IC][XN_STR];             // 4.3KB
    __shared__ __align__(8)  unsigned short sh_kp[BT / 2][KP_STR];         // 1.3KB

    const int tid   = threadIdx.x;
    const int opair = tid & 3;           // o = o0 + 2*opair (+0/1)
    const int bpair = tid >> 2;          // 0..31 -> b = b0 + 2*bpair (+0/1)
    const int o0    = blockIdx.x * OT;
    const int opg0  = blockIdx.x * (OT / 2);     // global o-pair base
    const int b0    = blockIdx.y * BT;
    const int i00   = blockIdx.z * IPART;

    float acc00 = 0.f, acc01 = 0.f, acc10 = 0.f, acc11 = 0.f;

#pragma unroll 1
    for (int c = 0; c < NCH; c++) {
        const int i0 = i00 + c * IC;

        // ---- stage xn: 16 ii x 64 b floats (4KB), float4 granularity ----
#pragma unroll
        for (int j = 0; j < 2; j++) {
            int e  = tid + j * 128;          // 0..255
            int ii = e >> 4;
            int b4 = (e & 15) * 4;
            float4 v = *(const float4*)&g_xn[(i0 + ii) * B_DIM + b0 + b4];
            *(float4*)&sh_xn[ii][b4] = v;
        }
        // ---- stage k-pack: 32 bpairs x 16 ii u16 (1KB), uint2 granularity ----
        {
            int pr = tid >> 2;
            int i4 = (tid & 3) * 4;
            *(uint2*)&sh_kp[pr][i4] =
                *(const uint2*)&g_kp[(b0 / 2 + pr) * IN_DIM + i0 + i4];
        }
        // ---- stage AB cells: 10 k x 4 op x 16 ii float4 (10.2KB) ----
#pragma unroll
        for (int un = 0; un < 5; un++) {
            int e  = tid + un * 128;         // 0..639
            int ii = e & 15;
            int op = (e >> 4) & 3;
            int k  = e >> 6;
            float4 v = *(const float4*)&g_ABP[k][(opg0 + op) * IN_DIM + i0 + ii];
            *(((float4*)sh_ab) + ii * AB_F4_PER_II + op * 10 + k) = v;
        }
        __syncthreads();

        // ---- consume: 4 triples (2b x 2o) per ii per thread ----
        const char* rbase = (const char*)sh_ab + opair * 160;
#pragma unroll
        for (int ii = 0; ii < IC; ii++) {
            float2 xn2 = *(const float2*)&sh_xn[ii][2 * bpair];
            unsigned int kk = sh_kp[bpair][ii];
            const char* rp = rbase + ii * (AB_F4_PER_II * 16);
            float4 sbq = *(const float4*)(rp + 144);           // {s,b',s',b''}
            float4 gA  = *(const float4*)(rp + (kk & 0xFFu));  // {A,B,A',B'} @ k0 (b)
            float4 gB  = *(const float4*)(rp + (kk >> 8));     // {A,B,A',B'} @ k1 (b+1)
            float t00 = sbq.x * xn2.x;      // (o , b)
            float t01 = sbq.z * xn2.x;      // (o', b)
            float t10 = sbq.x * xn2.y;      // (o , b+1)
            float t11 = sbq.z * xn2.y;      // (o', b+1)
            float u00 = ex2_f(t00), r00 = rcp_f(u00);
            float u01 = ex2_f(t01), r01 = rcp_f(u01);
            float u10 = ex2_f(t10), r10 = rcp_f(u10);
            float u11 = ex2_f(t11), r11 = rcp_f(u11);
            acc00 = fmaf(gA.x, r00, fmaf(gA.y, u00, fmaf(sbq.y, xn2.x, acc00)));
            acc01 = fmaf(gA.z, r01, fmaf(gA.w, u01, fmaf(sbq.w, xn2.x, acc01)));
            acc10 = fmaf(gB.x, r10, fmaf(gB.y, u10, fmaf(sbq.y, xn2.y, acc10)));
            acc11 = fmaf(gB.z, r11, fmaf(gB.w, u11, fmaf(sbq.w, xn2.y, acc11)));
        }
        __syncthreads();
    }

    // Z=8: one-shot commutative atomic adds from a zeroed buffer -> deterministic
    int b = b0 + 2 * bpair;
    int o = o0 + 2 * opair;
    atomicAdd(&out[b * OUT_DIM + o],           acc00);
    atomicAdd(&out[b * OUT_DIM + o + 1],       acc01);
    atomicAdd(&out[(b + 1) * OUT_DIM + o],     acc10);
    atomicAdd(&out[(b + 1) * OUT_DIM + o + 1], acc11);
}

// ---------------------------------------------------------------------------
extern "C" void kernel_launch(void* const* d_in, const int* in_sizes, int n_in,
                              void* d_out, int out_size)
{
    const float* x      = (const float*)d_in[0];
    const float* w      = (const float*)d_in[1];
    const float* scaler = (const float*)d_in[2];
    const float* base   = (const float*)d_in[3];
    const float* grid   = (const float*)d_in[4];
    float* out = (float*)d_out;

    k_prep<<<384, 256>>>(x, w, scaler, base, grid, out);
    dim3 g(OUT_DIM / OT, B_DIM / BT, Z);    // 32 x 4 x 8 = 1024 CTAs
    k_main<<<g, 128>>>(out);
}

// round 15
// speedup vs baseline: 1.0440x; 1.0425x over previous
#include <cuda_runtime.h>

#define B_DIM   256
#define OUT_DIM 256
#define IN_DIM  256
#define G_DIM   8
#define LOG2E   1.44269504088896340736f
#define LN2     0.69314718055994530942f

#define OT    8          // o per CTA (4 o-pairs)
#define BT    64         // b per CTA (32 b-pairs)
#define IC    16         // i-chunk
#define Z     8
#define IPART (IN_DIM / Z)      // 32
#define NCH   (IPART / IC)      // 2

// shared layout constants
#define AB_F4_PER_II 41         // 4 opairs * 10 float4 + 1 pad  (656B per ii)
#define XN_STR 68               // floats per ii row (272B, 16B-mult)

// Precomputed scratch (device globals; no allocation).
// g_xn[i][b]: tanh(x)*log2e with low mantissa byte REPLACED by koff = k*16
// (k = #grid pts <= xn, 0..8 -> koff 0..128; perturbs xn by <= 2^-16 relative)
__device__ float  g_xn[IN_DIM * B_DIM];
__device__ float4 g_ABP[10][(OUT_DIM / 2) * IN_DIM];
// g_ABP[k][op*IN+i]: k<9 -> {A_k(2op), B_k(2op), A_k(2op+1), B_k(2op+1)}
//                    k=9 -> {s(2op), b'(2op), s(2op+1), b'(2op+1)}   (b' = base*ln2)

__device__ __forceinline__ float rcp_f(float a) {
    float r; asm("rcp.approx.f32 %0, %1;" : "=f"(r) : "f"(a)); return r;
}
__device__ __forceinline__ float ex2_f(float a) {
    float r; asm("ex2.approx.f32 %0, %1;" : "=f"(r) : "f"(a)); return r;
}
__device__ __forceinline__ float tanh_fast(float x) {
    float e = __expf(2.0f * x);                 // saturates correctly at +/-inf
    return 1.0f - __fdividef(2.0f, e + 1.0f);
}
// replace low mantissa byte of v with koff (0..255)
__device__ __forceinline__ float stuff_koff(float v, int koff) {
    unsigned int u = (__float_as_uint(v) & 0xFFFFFF00u) | (unsigned int)koff;
    return __uint_as_float(u);
}

// ---------------------------------------------------------------------------
// Prep (R12 structure): blocks [0,128) -> xn/k (stuffed);
// blocks [128,256) -> o-paired A/B tables (coalesced float4 writes) + zero out.
// ---------------------------------------------------------------------------
__global__ __launch_bounds__(256)
void k_prep(const float* __restrict__ x,
            const float* __restrict__ w,
            const float* __restrict__ scaler,
            const float* __restrict__ base_,
            const float* __restrict__ grid,
            float* __restrict__ out)
{
    const float g0    = __ldg(grid);
    const float g7    = __ldg(grid + (G_DIM - 1));
    const float step  = (g7 - g0) * (1.0f / (float)(G_DIM - 1));
    const float inv_h = (float)(G_DIM - 1) / (g7 - g0);

    if (blockIdx.x < 128) {
        // ---- xn / k (stuffed into low mantissa byte) ----
        int u    = blockIdx.x * 256 + threadIdx.x;   // 0..32767
        int pair = u >> 8;                           // 0..127
        int i    = u & 255;
        int b    = pair * 2;
        float xn0 = tanh_fast(x[b * IN_DIM + i]) * LOG2E;
        float xn1 = tanh_fast(x[(b + 1) * IN_DIM + i]) * LOG2E;
        // k from the unscaled tanh: xn' = xn*log2e, compare in scaled domain
        int k0 = 1 + __float2int_rd((xn0 - g0 * LOG2E) * (inv_h / LOG2E));
        int k1 = 1 + __float2int_rd((xn1 - g0 * LOG2E) * (inv_h / LOG2E));
        k0 = max(0, min(8, k0));
        k1 = max(0, min(8, k1));
        *(float2*)&g_xn[i * B_DIM + b] =
            make_float2(stuff_koff(xn0, k0 * 16), stuff_koff(xn1, k1 * 16));
    } else {
        // ---- paired A/B prefix tables (2 o's per thread) + zero the output ----
        int v  = (blockIdx.x - 128) * 256 + threadIdx.x;  // op*IN + i, 0..32767
        ((float2*)out)[v] = make_float2(0.f, 0.f);        // zero out (replaces memset)

        int op = v >> 8;
        int i  = v & 255;
        float Aab[2][9], Bab[2][9], sv[2], bv[2];
#pragma unroll
        for (int h = 0; h < 2; h++) {
            int row = (2 * op + h) * IN_DIM + i;
            float s = scaler[row];
            float4 w0 = *(const float4*)(w + row * G_DIM);
            float4 w1 = *(const float4*)(w + row * G_DIM + 4);
            float wv[G_DIM] = {w0.x, w0.y, w0.z, w0.w, w1.x, w1.y, w1.z, w1.w};
            float Ep = __expf(s * step);
            float ep = __expf(s * g0);
            float Eq = rcp_f(Ep);
            float eq = rcp_f(ep);
            float p[G_DIM], q[G_DIM];
#pragma unroll
            for (int g = 0; g < G_DIM; g++) {
                p[g] = wv[g] * ep;  ep *= Ep;   // w_g * e^{ s*grid_g}
                q[g] = wv[g] * eq;  eq *= Eq;   // w_g * e^{-s*grid_g}
            }
            Aab[h][0] = 0.f;
#pragma unroll
            for (int k = 0; k < 8; k++) Aab[h][k + 1] = Aab[h][k] + p[k];
            Bab[h][8] = 0.f;
#pragma unroll
            for (int k = 7; k >= 0; k--) Bab[h][k] = Bab[h][k + 1] + q[k];
            sv[h] = s;
            bv[h] = base_[row] * LN2;
        }
#pragma unroll
        for (int k = 0; k < 9; k++)
            g_ABP[k][v] = make_float4(Aab[0][k], Bab[0][k], Aab[1][k], Bab[1][k]);
        g_ABP[9][v] = make_float4(sv[0], bv[0], sv[1], bv[1]);
    }
}

// ---------------------------------------------------------------------------
// Main: CTA = 64b x 8o x IPART i; thread = (2b x 2o); stage + consume.
//   contribution = A_k*2^{-t} + B_k*2^{t} + b'*xn',  t = s*xn'
// koff gathered from xn's stuffed low mantissa byte (no separate k array).
// ---------------------------------------------------------------------------
__global__ __launch_bounds__(128, 8)
void k_main(float* __restrict__ out)
{
    __shared__ __align__(16) float sh_ab[IC * AB_F4_PER_II * 4];  // 10.5KB
    __shared__ __align__(16) float sh_xn[IC][XN_STR];             // 4.3KB

    const int tid   = threadIdx.x;
    const int opair = tid & 3;           // o = o0 + 2*opair (+0/1)
    const int bpair = tid >> 2;          // 0..31 -> b = b0 + 2*bpair (+0/1)
    const int o0    = blockIdx.x * OT;
    const int opg0  = blockIdx.x * (OT / 2);     // global o-pair base
    const int b0    = blockIdx.y * BT;
    const int i00   = blockIdx.z * IPART;

    float acc00 = 0.f, acc01 = 0.f, acc10 = 0.f, acc11 = 0.f;

#pragma unroll 1
    for (int c = 0; c < NCH; c++) {
        const int i0 = i00 + c * IC;

        // ---- stage xn: 16 ii x 64 b floats (4KB), float4 granularity ----
#pragma unroll
        for (int j = 0; j < 2; j++) {
            int e  = tid + j * 128;          // 0..255
            int ii = e >> 4;
            int b4 = (e & 15) * 4;
            float4 v = *(const float4*)&g_xn[(i0 + ii) * B_DIM + b0 + b4];
            *(float4*)&sh_xn[ii][b4] = v;
        }
        // ---- stage AB cells: 10 k x 4 op x 16 ii float4 (10.2KB) ----
#pragma unroll
        for (int un = 0; un < 5; un++) {
            int e  = tid + un * 128;         // 0..639
            int ii = e & 15;
            int op = (e >> 4) & 3;
            int k  = e >> 6;
            float4 v = *(const float4*)&g_ABP[k][(opg0 + op) * IN_DIM + i0 + ii];
            *(((float4*)sh_ab) + ii * AB_F4_PER_II + op * 10 + k) = v;
        }
        __syncthreads();

        // ---- consume: 4 triples (2b x 2o) per ii per thread ----
        const char* rbase = (const char*)sh_ab + opair * 160;
#pragma unroll
        for (int ii = 0; ii < IC; ii++) {
            float2 xn2 = *(const float2*)&sh_xn[ii][2 * bpair];
            unsigned int k0off = __float_as_uint(xn2.x) & 0xFFu;   // k0*16
            unsigned int k1off = __float_as_uint(xn2.y) & 0xFFu;   // k1*16
            const char* rp = rbase + ii * (AB_F4_PER_II * 16);
            float4 sbq = *(const float4*)(rp + 144);       // {s,b',s',b''}
            float4 gA  = *(const float4*)(rp + k0off);     // {A,B,A',B'} @ k0 (b)
            float4 gB  = *(const float4*)(rp + k1off);     // {A,B,A',B'} @ k1 (b+1)
            float t00 = sbq.x * xn2.x;      // (o , b)
            float t01 = sbq.z * xn2.x;      // (o', b)
            float t10 = sbq.x * xn2.y;      // (o , b+1)
            float t11 = sbq.z * xn2.y;      // (o', b+1)
            float u00 = ex2_f(t00), r00 = rcp_f(u00);
            float u01 = ex2_f(t01), r01 = rcp_f(u01);
            float u10 = ex2_f(t10), r10 = rcp_f(u10);
            float u11 = ex2_f(t11), r11 = rcp_f(u11);
            acc00 = fmaf(gA.x, r00, fmaf(gA.y, u00, fmaf(sbq.y, xn2.x, acc00)));
            acc01 = fmaf(gA.z, r01, fmaf(gA.w, u01, fmaf(sbq.w, xn2.x, acc01)));
            acc10 = fmaf(gB.x, r10, fmaf(gB.y, u10, fmaf(sbq.y, xn2.y, acc10)));
            acc11 = fmaf(gB.z, r11, fmaf(gB.w, u11, fmaf(sbq.w, xn2.y, acc11)));
        }
        __syncthreads();
    }

    // Z=8: one-shot commutative atomic adds from a zeroed buffer
    int b = b0 + 2 * bpair;
    int o = o0 + 2 * opair;
    atomicAdd(&out[b * OUT_DIM + o],           acc00);
    atomicAdd(&out[b * OUT_DIM + o + 1],       acc01);
    atomicAdd(&out[(b + 1) * OUT_DIM + o],     acc10);
    atomicAdd(&out[(b + 1) * OUT_DIM + o + 1], acc11);
}

// ---------------------------------------------------------------------------
extern "C" void kernel_launch(void* const* d_in, const int* in_sizes, int n_in,
                              void* d_out, int out_size)
{
    const float* x      = (const float*)d_in[0];
    const float* w      = (const float*)d_in[1];
    const float* scaler = (const float*)d_in[2];
    const float* base   = (const float*)d_in[3];
    const float* grid   = (const float*)d_in[4];
    float* out = (float*)d_out;

    k_prep<<<256, 256>>>(x, w, scaler, base, grid, out);
    dim3 g(OUT_DIM / OT, B_DIM / BT, Z);    // 32 x 4 x 8 = 1024 CTAs
    k_main<<<g, 128>>>(out);
}